// round 15
// baseline (speedup 1.0000x reference)
#include <cuda_runtime.h>
#include <cuda_bf16.h>
#include <math.h>
#include <stdint.h>

// Problem constants
#define S_    2048
#define B_    16
#define H_    512
#define L_    4096
#define LAB_  256
#define V_    32000

// cls: persistent grid, rowblock-major work items, 128 threads (4 warps 2x2)
#define CLS_BM    64
#define CLS_BN    128
#define CLS_GRID  444                 // 3 CTAs x 148 SMs, one wave
#define N_RB      (L_ / CLS_BM)       // 64 rowblocks
#define N_VT      (V_ / CLS_BN)       // 250 v-tiles
#define N_ITEMS   (N_RB * N_VT)       // 16000

// cls smem (bytes)
#define AS_LDB   528                  // A row stride bytes (264 bf16)
#define BS_LDB   272                  // B row stride bytes (136 bf16)
#define CLS_A_OFF 0
#define CLS_A_BYTES (CLS_BM * AS_LDB)        // 33792
#define CLS_B_OFF  CLS_A_BYTES
#define CLS_B_TILE (32 * BS_LDB)             // 8704
#define CLS_B_BYTES (4 * CLS_B_TILE)         // 34816 (4-stage ring)
#define CLS_SMEM (CLS_B_OFF + CLS_B_BYTES)   // 68608 -> 3 CTAs/SM

// wgemm (raw mma): BM=32, BN=64, 128 threads (2x2 warps, 16x32 tiles)
#define WGA_LDB 80                    // A row stride bytes (32 bf16 + 16B pad)
#define WGB_LDB 144                   // B row stride bytes (64 bf16 + pad)
#define WG_A_BYTES (32 * WGA_LDB)     // 2560
#define WG_STAGE (WG_A_BYTES + 32 * WGB_LDB) // 7168
#define WG_SMEM_BYTES (4 * WG_STAGE)  // 28672 (under 48KB default)

// Scratch (static device globals)
__device__ __nv_bfloat16 g_spanb[(size_t)L_ * 3 * H_];
__device__ __nv_bfloat16 g_h1b[(size_t)L_ * LAB_];
__device__ float g_feat[(size_t)L_ * LAB_];
__device__ __nv_bfloat16 g_featb[(size_t)L_ * LAB_];
__device__ __nv_bfloat16 g_w1b[(size_t)3 * H_ * LAB_];
__device__ __nv_bfloat16 g_w2b[(size_t)LAB_ * LAB_];
__device__ __nv_bfloat16 g_wob[(size_t)LAB_ * V_];      // Wo bf16 [256][32000]
__device__ float g_rowsum[L_];                          // per-row exp sums

// ---------------------------------------------------------------------------
// PTX primitives (sm80-baseline)
// ---------------------------------------------------------------------------
__device__ __forceinline__ uint32_t smem_u32(const void* p) {
    uint32_t a;
    asm("{ .reg .u64 t; cvta.to.shared.u64 t, %1; cvt.u32.u64 %0, t; }"
        : "=r"(a) : "l"(p));
    return a;
}
__device__ __forceinline__ void ldsm_x4(uint32_t r[4], uint32_t addr) {
    asm volatile("ldmatrix.sync.aligned.m8n8.x4.shared.b16 {%0,%1,%2,%3}, [%4];"
        : "=r"(r[0]), "=r"(r[1]), "=r"(r[2]), "=r"(r[3]) : "r"(addr));
}
__device__ __forceinline__ void ldsm_x4_t(uint32_t r[4], uint32_t addr) {
    asm volatile("ldmatrix.sync.aligned.m8n8.x4.trans.shared.b16 {%0,%1,%2,%3}, [%4];"
        : "=r"(r[0]), "=r"(r[1]), "=r"(r[2]), "=r"(r[3]) : "r"(addr));
}
__device__ __forceinline__ void mma_bf16(float d[4], const uint32_t a[4],
                                         uint32_t b0, uint32_t b1) {
    asm volatile(
        "mma.sync.aligned.m16n8k16.row.col.f32.bf16.bf16.f32 "
        "{%0,%1,%2,%3}, {%4,%5,%6,%7}, {%8,%9}, {%0,%1,%2,%3};"
        : "+f"(d[0]), "+f"(d[1]), "+f"(d[2]), "+f"(d[3])
        : "r"(a[0]), "r"(a[1]), "r"(a[2]), "r"(a[3]), "r"(b0), "r"(b1));
}
#define CP_ASYNC16(dst, src) \
    asm volatile("cp.async.cg.shared.global [%0], [%1], 16;" \
        :: "r"(dst), "l"(src) : "memory")
#define CP_COMMIT() asm volatile("cp.async.commit_group;" ::: "memory")
#define CP_WAIT2()  asm volatile("cp.async.wait_group 2;" ::: "memory")
#define CP_WAITALL() asm volatile("cp.async.wait_group 0;" ::: "memory")

__device__ __forceinline__ float ex2f(float x) {
    float r;
    asm("ex2.approx.f32 %0, %1;" : "=f"(r) : "f"(x));
    return r;
}

// ---------------------------------------------------------------------------
// fast exp poly (sigmoid epilogue in wgemm)
// ---------------------------------------------------------------------------
__device__ __forceinline__ float fast_exp(float x) {
    float z = x * 1.4426950408889634f;
    float r = rintf(z);
    float f = z - r;
    float p = 1.3333558146428443e-3f;
    p = fmaf(p, f, 9.6181291976036120e-3f);
    p = fmaf(p, f, 5.5504108664821580e-2f);
    p = fmaf(p, f, 2.4022650695910072e-1f);
    p = fmaf(p, f, 6.9314718055994531e-1f);
    p = fmaf(p, f, 1.0f);
    return __int_as_float(((int)r + 127) << 23) * p;
}

// ---------------------------------------------------------------------------
// span embeddings -> bf16 (float4, 4-way unrolled gather)
// ---------------------------------------------------------------------------
__global__ void span_kernel(const float* __restrict__ hidden,
                            const int* __restrict__ begins,
                            const int* __restrict__ ends,
                            const int* __restrict__ bids) {
    const int l = blockIdx.x;
    const int beg = begins[l];
    const int end = ends[l];
    const int b   = bids[l];
    const float inv_len = 1.0f / (float)(end - beg);
    const float4* hp = (const float4*)hidden;
    const int h4 = threadIdx.x;
    const int H4 = H_ / 4;

    float4 left  = hp[((size_t)(beg - 1) * B_ + b) * H4 + h4];
    float4 right = hp[((size_t)end * B_ + b) * H4 + h4];
    float4 s0 = make_float4(0.f, 0.f, 0.f, 0.f);
    float4 s1 = make_float4(0.f, 0.f, 0.f, 0.f);
    float4 s2 = make_float4(0.f, 0.f, 0.f, 0.f);
    float4 s3 = make_float4(0.f, 0.f, 0.f, 0.f);
    int t = beg;
    for (; t + 4 <= end; t += 4) {
        float4 v0 = hp[((size_t)t * B_ + b) * H4 + h4];
        float4 v1 = hp[((size_t)(t + 1) * B_ + b) * H4 + h4];
        float4 v2 = hp[((size_t)(t + 2) * B_ + b) * H4 + h4];
        float4 v3 = hp[((size_t)(t + 3) * B_ + b) * H4 + h4];
        s0.x += v0.x; s0.y += v0.y; s0.z += v0.z; s0.w += v0.w;
        s1.x += v1.x; s1.y += v1.y; s1.z += v1.z; s1.w += v1.w;
        s2.x += v2.x; s2.y += v2.y; s2.z += v2.z; s2.w += v2.w;
        s3.x += v3.x; s3.y += v3.y; s3.z += v3.z; s3.w += v3.w;
    }
    for (; t < end; ++t) {
        float4 v0 = hp[((size_t)t * B_ + b) * H4 + h4];
        s0.x += v0.x; s0.y += v0.y; s0.z += v0.z; s0.w += v0.w;
    }
    s0.x += s1.x + s2.x + s3.x;
    s0.y += s1.y + s2.y + s3.y;
    s0.z += s1.z + s2.z + s3.z;
    s0.w += s1.w + s2.w + s3.w;

    __nv_bfloat16* out = g_spanb + (size_t)l * (3 * H_);
    uint2 pk;
    pk.x = __nv_bfloat162_raw(__floats2bfloat162_rn(left.x, left.y)).x;
    pk.y = __nv_bfloat162_raw(__floats2bfloat162_rn(left.z, left.w)).x;
    *(uint2*)&out[h4 * 4] = pk;
    pk.x = __nv_bfloat162_raw(__floats2bfloat162_rn(s0.x * inv_len, s0.y * inv_len)).x;
    pk.y = __nv_bfloat162_raw(__floats2bfloat162_rn(s0.z * inv_len, s0.w * inv_len)).x;
    *(uint2*)&out[H_ + h4 * 4] = pk;
    pk.x = __nv_bfloat162_raw(__floats2bfloat162_rn(right.x, right.y)).x;
    pk.y = __nv_bfloat162_raw(__floats2bfloat162_rn(right.z, right.w)).x;
    *(uint2*)&out[2 * H_ + h4 * 4] = pk;
}

// ---------------------------------------------------------------------------
// prep: W1+W2 -> bf16, zero out + g_rowsum (fused launches)
// ---------------------------------------------------------------------------
#define N1_4 (3 * H_ * LAB_ / 4)
#define N2_4 (LAB_ * LAB_ / 4)
__global__ void prep_kernel(const float* __restrict__ W1,
                            const float* __restrict__ W2,
                            float* __restrict__ out) {
    int i = blockIdx.x * blockDim.x + threadIdx.x;
    if (i == 0) out[0] = 0.0f;
    if (i < L_) g_rowsum[i] = 0.0f;
    if (i < N1_4) {
        float4 v = ((const float4*)W1)[i];
        ((__nv_bfloat162*)g_w1b)[2 * i]     = __floats2bfloat162_rn(v.x, v.y);
        ((__nv_bfloat162*)g_w1b)[2 * i + 1] = __floats2bfloat162_rn(v.z, v.w);
    } else if (i < N1_4 + N2_4) {
        int j = i - N1_4;
        float4 v = ((const float4*)W2)[j];
        ((__nv_bfloat162*)g_w2b)[2 * j]     = __floats2bfloat162_rn(v.x, v.y);
        ((__nv_bfloat162*)g_w2b)[2 * j + 1] = __floats2bfloat162_rn(v.z, v.w);
    }
}

// ---------------------------------------------------------------------------
// fp32 -> bf16 conversion (Wo)
// ---------------------------------------------------------------------------
__global__ void cvt_kernel(const float* __restrict__ src,
                           __nv_bfloat16* __restrict__ dst, int n4) {
    int i = blockIdx.x * blockDim.x + threadIdx.x;
    if (i < n4) {
        float4 v = ((const float4*)src)[i];
        ((__nv_bfloat162*)dst)[2 * i]     = __floats2bfloat162_rn(v.x, v.y);
        ((__nv_bfloat162*)dst)[2 * i + 1] = __floats2bfloat162_rn(v.z, v.w);
    }
}

// ---------------------------------------------------------------------------
// wgemm (raw mma.sync): C[M,N] = epi(A[M,K] @ B[K,N] + bias)
// BM=32, BN=64, 128 threads = 4 warps (2x2), warp tile 16x32.
// 4-stage K=32 cp.async ring; direct register epilogue.
// grid (M/32, N/64) = (128, 4) = 512 CTAs.
// ---------------------------------------------------------------------------
template<int K, int EPI>
__global__ __launch_bounds__(128)
void wgemm_kernel(const __nv_bfloat16* __restrict__ A,
                  const __nv_bfloat16* __restrict__ B,
                  const float* __restrict__ bias,
                  float* __restrict__ C32,
                  __nv_bfloat16* __restrict__ Cb, int N) {
    extern __shared__ char smem[];
    const uint32_t sb = smem_u32(smem);

    const int tid = threadIdx.x;
    const int wid = tid >> 5;
    const int lane = tid & 31;
    const int wm = wid >> 1;     // 0..1 (row group of 16)
    const int wn = wid & 1;      // 0..1 (col group of 32)
    const int m0 = blockIdx.x * 32;
    const int n0 = blockIdx.y * 64;
    constexpr int NIT = K / 32;

    auto issue = [&](int g) {
        const int k0 = g * 32;
        const uint32_t st = sb + (g & 3) * WG_STAGE;
        // A: 32 rows x 32 bf16 = 128 x 16B chunks, 1 per thread
        {
            int r = tid >> 2, kc = tid & 3;
            CP_ASYNC16(st + r * WGA_LDB + kc * 16,
                       (const char*)&A[(size_t)(m0 + r) * K + k0 + kc * 8]);
        }
        // B: 32 k-rows x 64 cols = 256 x 16B chunks, 2 per thread
#pragma unroll
        for (int i = 0; i < 2; ++i) {
            int c = tid + i * 128;
            int rk = c >> 3, cc = c & 7;
            CP_ASYNC16(st + WG_A_BYTES + rk * WGB_LDB + cc * 16,
                       (const char*)&B[(size_t)(k0 + rk) * N + n0 + cc * 8]);
        }
    };

    const uint32_t aBase = sb + (wm * 16 + (lane & 15)) * WGA_LDB
                         + (lane >> 4) * 16;
    uint32_t bBase[2];
#pragma unroll
    for (int ng = 0; ng < 2; ++ng)
        bBase[ng] = sb + WG_A_BYTES + (lane & 15) * WGB_LDB
                  + (wn * 32 + ng * 16) * 2 + (lane >> 4) * 16;

    float acc[4][4];
#pragma unroll
    for (int ni = 0; ni < 4; ++ni)
#pragma unroll
        for (int j = 0; j < 4; ++j) acc[ni][j] = 0.0f;

#pragma unroll
    for (int st = 0; st < 3; ++st) { issue(st); CP_COMMIT(); }

    for (int g = 0; g < NIT; ++g) {
        CP_WAIT2();
        __syncthreads();
        if (g + 3 < NIT) issue(g + 3);
        CP_COMMIT();
        const uint32_t stOff = (g & 3) * WG_STAGE;
#pragma unroll
        for (int s = 0; s < 2; ++s) {
            uint32_t a[4], bb[2][4];
            ldsm_x4(a, aBase + stOff + s * 32);
#pragma unroll
            for (int ng = 0; ng < 2; ++ng)
                ldsm_x4_t(bb[ng], bBase[ng] + stOff + s * 16 * WGB_LDB);
#pragma unroll
            for (int ni = 0; ni < 4; ++ni)
                mma_bf16(acc[ni], a,
                         bb[ni >> 1][(ni & 1) * 2],
                         bb[ni >> 1][(ni & 1) * 2 + 1]);
        }
        __syncthreads();
    }
    CP_WAITALL();

    // direct register epilogue (m16n8k16 acc lane mapping)
    {
        const int r0 = m0 + wm * 16 + (lane >> 2);
#pragma unroll
        for (int ni = 0; ni < 4; ++ni) {
            const int gc = n0 + wn * 32 + ni * 8 + (lane & 3) * 2;
            float2 bv = *(const float2*)&bias[gc];
            float v00 = acc[ni][0] + bv.x;
            float v01 = acc[ni][1] + bv.y;
            float v10 = acc[ni][2] + bv.x;
            float v11 = acc[ni][3] + bv.y;
            if (EPI == 1) {
                v00 = 1.0f / (1.0f + fast_exp(-v00));
                v01 = 1.0f / (1.0f + fast_exp(-v01));
                v10 = 1.0f / (1.0f + fast_exp(-v10));
                v11 = 1.0f / (1.0f + fast_exp(-v11));
                *(__nv_bfloat162*)&Cb[(size_t)r0 * N + gc] =
                    __floats2bfloat162_rn(v00, v01);
                *(__nv_bfloat162*)&Cb[(size_t)(r0 + 8) * N + gc] =
                    __floats2bfloat162_rn(v10, v11);
            } else {
                *(float2*)&C32[(size_t)r0 * N + gc] = make_float2(v00, v01);
                *(float2*)&C32[(size_t)(r0 + 8) * N + gc] = make_float2(v10, v11);
                *(__nv_bfloat162*)&Cb[(size_t)r0 * N + gc] =
                    __floats2bfloat162_rn(v00, v01);
                *(__nv_bfloat162*)&Cb[(size_t)(r0 + 8) * N + gc] =
                    __floats2bfloat162_rn(v10, v11);
            }
        }
    }
}

// ---------------------------------------------------------------------------
// cls: PERSISTENT mma.sync bf16 classifier GEMM + fused per-row exp-sums.
// BM=64, 128 threads = 4 warps (2x2), warp tile 32x64.
// grid = 444 (3 CTAs/SM). Work = 16000 items (rb, vtile), rowblock-major.
// ---------------------------------------------------------------------------
__global__ __launch_bounds__(128, 3)
void cls_kernel(const float* __restrict__ bo) {
    extern __shared__ char smem[];
    const uint32_t sb = smem_u32(smem);

    const int tid = threadIdx.x;
    const int wid = tid >> 5;
    const int lane = tid & 31;
    const int wm = wid >> 1;          // 0..1 (row group of 32)
    const int wn = wid & 1;           // 0..1 (col group of 64)
    const float LOG2E = 1.4426950408889634f;

    const int start = ((long long)blockIdx.x * N_ITEMS) / CLS_GRID;
    const int end   = ((long long)(blockIdx.x + 1) * N_ITEMS) / CLS_GRID;
    const int NST   = (end - start) * 8;

    uint32_t aBase[2];
#pragma unroll
    for (int mi = 0; mi < 2; ++mi)
        aBase[mi] = sb + CLS_A_OFF
                  + (wm * 32 + mi * 16 + (lane & 15)) * AS_LDB
                  + (lane >> 4) * 16;
    uint32_t bBase[4];
#pragma unroll
    for (int ng = 0; ng < 4; ++ng)
        bBase[ng] = sb + CLS_B_OFF + (lane & 15) * BS_LDB
                  + (wn * 64 + ng * 16) * 2 + (lane >> 4) * 16;

    auto issue_stage = [&](int gs) {
        const int item = start + (gs >> 3);
        const int k0 = (gs & 7) * 32;
        const int v0 = (item % N_VT) * CLS_BN;
        const uint32_t dbase = sb + CLS_B_OFF + (gs & 3) * CLS_B_TILE;
#pragma unroll
        for (int i = 0; i < 4; ++i) {
            int c = tid + i * 128;
            int row = c >> 4, col = c & 15;
            CP_ASYNC16(dbase + row * BS_LDB + col * 16,
                       (const char*)(g_wob + (size_t)(k0 + row) * V_
                                     + v0 + col * 8));
        }
    };

#pragma unroll
    for (int st = 0; st < 3; ++st) { issue_stage(st); CP_COMMIT(); }

    float rAcc[2][2];
#pragma unroll
    for (int mi = 0; mi < 2; ++mi) { rAcc[mi][0] = 0.f; rAcc[mi][1] = 0.f; }

    float acc[2][8][4];
#pragma unroll
    for (int mi = 0; mi < 2; ++mi)
#pragma unroll
        for (int ni = 0; ni < 8; ++ni)
#pragma unroll
            for (int j = 0; j < 4; ++j) acc[mi][ni][j] = 0.0f;

    int cur_rb = -1;

    auto flush = [&](int rb) {
#pragma unroll
        for (int mi = 0; mi < 2; ++mi)
#pragma unroll
            for (int hi = 0; hi < 2; ++hi) {
                float v = rAcc[mi][hi];
                v += __shfl_xor_sync(0xFFFFFFFFu, v, 1);
                v += __shfl_xor_sync(0xFFFFFFFFu, v, 2);
                if ((lane & 3) == 0)
                    atomicAdd(&g_rowsum[rb * CLS_BM + wm * 32 + mi * 16
                                        + hi * 8 + (lane >> 2)], v);
                rAcc[mi][hi] = 0.0f;
            }
    };

    for (int gs = 0; gs < NST; ++gs) {
        CP_WAIT2();
        __syncthreads();
        if (gs + 3 < NST) issue_stage(gs + 3);
        CP_COMMIT();

        const int item = start + (gs >> 3);
        if ((gs & 7) == 0) {
            const int rb = item / N_VT;
            if (rb != cur_rb) {
                if (cur_rb >= 0) flush(cur_rb);
                // stage A: 64 rows x 32 uint4 chunks = 2048, 16 per thread
                const __nv_bfloat16* src = g_featb + (size_t)rb * CLS_BM * LAB_;
#pragma unroll
                for (int t = tid; t < CLS_BM * 32; t += 128) {
                    int r = t >> 5, k8 = t & 31;
                    uint4 v = *(const uint4*)&src[(size_t)r * LAB_ + k8 * 8];
                    *(uint4*)(smem + CLS_A_OFF + r * AS_LDB + k8 * 16) = v;
                }
                __syncthreads();
                cur_rb = rb;
            }
        }

        const uint32_t bufOff = (gs & 3) * CLS_B_TILE;
        const uint32_t aOff = (gs & 7) * 64;
#pragma unroll
        for (int s = 0; s < 2; ++s) {
            uint32_t a[2][4], bb[4][4];
#pragma unroll
            for (int mi = 0; mi < 2; ++mi)
                ldsm_x4(a[mi], aBase[mi] + aOff + s * 32);
#pragma unroll
            for (int ng = 0; ng < 4; ++ng)
                ldsm_x4_t(bb[ng], bBase[ng] + bufOff + s * 16 * BS_LDB);
#pragma unroll
            for (int mi = 0; mi < 2; ++mi)
#pragma unroll
                for (int ni = 0; ni < 8; ++ni)
                    mma_bf16(acc[mi][ni], a[mi],
                             bb[ni >> 1][(ni & 1) * 2],
                             bb[ni >> 1][(ni & 1) * 2 + 1]);
        }

        if ((gs & 7) == 7) {
            const int v0 = (item % N_VT) * CLS_BN;
            const float* bop = bo + v0 + wn * 64 + (lane & 3) * 2;
#pragma unroll
            for (int ni = 0; ni < 8; ++ni) {
                float2 bv = *(const float2*)(bop + ni * 8);
                float b0 = bv.x * LOG2E, b1 = bv.y * LOG2E;
#pragma unroll
                for (int mi = 0; mi < 2; ++mi) {
                    rAcc[mi][0] += ex2f(fmaf(acc[mi][ni][0], LOG2E, b0))
                                 + ex2f(fmaf(acc[mi][ni][1], LOG2E, b1));
                    rAcc[mi][1] += ex2f(fmaf(acc[mi][ni][2], LOG2E, b0))
                                 + ex2f(fmaf(acc[mi][ni][3], LOG2E, b1));
                    acc[mi][ni][0] = 0.f; acc[mi][ni][1] = 0.f;
                    acc[mi][ni][2] = 0.f; acc[mi][ni][3] = 0.f;
                }
            }
        }
    }
    CP_WAITALL();
    if (cur_rb >= 0) flush(cur_rb);
}

// ---------------------------------------------------------------------------
// loss: per-row fp32 tag logit + log(rowsum) + global sum
// ---------------------------------------------------------------------------
__global__ void loss_kernel(const float* __restrict__ Wo,
                            const float* __restrict__ bo,
                            const int* __restrict__ tags,
                            float* __restrict__ out) {
    const int warp = (blockIdx.x * blockDim.x + threadIdx.x) >> 5;
    const int lane = threadIdx.x & 31;
    const int nwarps = (gridDim.x * blockDim.x) >> 5;
    float local = 0.0f;
    for (int l = warp; l < L_; l += nwarps) {
        int tag = tags[l];
        float dot = 0.0f;
#pragma unroll
        for (int j = 0; j < 8; ++j) {
            int k = lane + j * 32;
            dot += g_feat[(size_t)l * 256 + k] * Wo[(size_t)k * V_ + tag];
        }
#pragma unroll
        for (int off = 16; off > 0; off >>= 1)
            dot += __shfl_down_sync(0xFFFFFFFFu, dot, off);
        if (lane == 0)
            local += logf(g_rowsum[l]) - (dot + bo[tag]);
    }
    if (lane == 0)
        atomicAdd(out, local * (1.0f / (4096.0f + 1e-5f)));
}

// ---------------------------------------------------------------------------
// Launch. Inputs: hidden, begins, ends, bids, tags, W1, b1, W2, b2, Wo, bo
// ---------------------------------------------------------------------------
extern "C" void kernel_launch(void* const* d_in, const int* in_sizes, int n_in,
                              void* d_out, int out_size) {
    const float* hidden = (const float*)d_in[0];
    const int*   begins = (const int*)d_in[1];
    const int*   ends   = (const int*)d_in[2];
    const int*   bids   = (const int*)d_in[3];
    const int*   tags   = (const int*)d_in[4];
    const float* W1     = (const float*)d_in[5];
    const float* b1     = (const float*)d_in[6];
    const float* W2     = (const float*)d_in[7];
    const float* b2     = (const float*)d_in[8];
    const float* Wo     = (const float*)d_in[9];
    const float* bo     = (const float*)d_in[10];
    float* out = (float*)d_out;

    __nv_bfloat16 *spanb, *h1b, *featb, *w1b, *w2b, *wob;
    float* feat;
    cudaGetSymbolAddress((void**)&spanb, g_spanb);
    cudaGetSymbolAddress((void**)&h1b, g_h1b);
    cudaGetSymbolAddress((void**)&feat, g_feat);
    cudaGetSymbolAddress((void**)&featb, g_featb);
    cudaGetSymbolAddress((void**)&w1b, g_w1b);
    cudaGetSymbolAddress((void**)&w2b, g_w2b);
    cudaGetSymbolAddress((void**)&wob, g_wob);

    // opt-in dynamic smem (cls only; wgemm fits the 48KB default)
    cudaFuncSetAttribute(cls_kernel,
                         cudaFuncAttributeMaxDynamicSharedMemorySize,
                         CLS_SMEM);

    // weight prep (bf16) + zero out + zero rowsums
    prep_kernel<<<(N1_4 + N2_4 + 255) / 256, 256>>>(W1, W2, out);
    cvt_kernel<<<(LAB_ * V_ / 4 + 255) / 256, 256>>>(Wo, wob, LAB_ * V_ / 4);

    // 1) span embeddings (bf16)
    span_kernel<<<L_, 128>>>(hidden, begins, ends, bids);

    // 2) h1 = sigmoid(span @ W1 + b1) -> bf16
    {
        dim3 grid(L_ / 32, LAB_ / 64);
        wgemm_kernel<3 * H_, 1><<<grid, 128, WG_SMEM_BYTES>>>(
            spanb, w1b, b1, nullptr, h1b, LAB_);
    }
    // 3) feat = h1 @ W2 + b2 -> fp32 + bf16
    {
        dim3 grid(L_ / 32, LAB_ / 64);
        wgemm_kernel<LAB_, 2><<<grid, 128, WG_SMEM_BYTES>>>(
            h1b, w2b, b2, feat, featb, LAB_);
    }
    // 4) persistent mma.sync classifier GEMM + fused exp-sum
    cls_kernel<<<CLS_GRID, 128, CLS_SMEM>>>(bo);

    // 5) final loss reduction
    loss_kernel<<<32, 256>>>(Wo, bo, tags, out);
}

// round 16
// speedup vs baseline: 1.0964x; 1.0964x over previous
#include <cuda_runtime.h>
#include <cuda_bf16.h>
#include <math.h>
#include <stdint.h>

// Problem constants
#define S_    2048
#define B_    16
#define H_    512
#define L_    4096
#define LAB_  256
#define V_    32000

// cls: persistent grid, rowblock-major work items, 128 threads (4 warps 2x2)
#define CLS_BM    128
#define CLS_BN    128
#define CLS_GRID  296                 // 2 CTAs x 148 SMs, one wave
#define N_RB      (L_ / CLS_BM)       // 32 rowblocks
#define N_VT      (V_ / CLS_BN)       // 250 v-tiles
#define N_ITEMS   (N_RB * N_VT)       // 8000

// cls smem (bytes)
#define AS_LDB   528                  // A row stride bytes (264 bf16)
#define BS_LDB   272                  // B row stride bytes (136 bf16)
#define CLS_A_OFF 0
#define CLS_A_BYTES (CLS_BM * AS_LDB)        // 67584
#define CLS_B_OFF  CLS_A_BYTES
#define CLS_B_TILE (32 * BS_LDB)             // 8704
#define CLS_B_BYTES (4 * CLS_B_TILE)         // 34816 (4-stage ring)
#define CLS_SMEM (CLS_B_OFF + CLS_B_BYTES)   // 102400 -> 2 CTAs/SM

// wgemm (raw mma): BM=64, BN=64, 128 threads (2x2 warps, 32x32 tiles)
// K=64 per stage, 4-stage ring
#define WGA_LDB 144                   // A row stride bytes (64 bf16 + 16B pad)
#define WGB_LDB 144                   // B row stride bytes (64 bf16 + pad)
#define WG_A_BYTES (64 * WGA_LDB)     // 9216
#define WG_STAGE (WG_A_BYTES + 64 * WGB_LDB) // 18432
#define WG_SMEM_BYTES (4 * WG_STAGE)  // 73728 (needs attribute)

// Scratch (static device globals)
__device__ __nv_bfloat16 g_spanb[(size_t)L_ * 3 * H_];
__device__ __nv_bfloat16 g_h1b[(size_t)L_ * LAB_];
__device__ float g_feat[(size_t)L_ * LAB_];
__device__ __nv_bfloat16 g_featb[(size_t)L_ * LAB_];
__device__ __nv_bfloat16 g_w1b[(size_t)3 * H_ * LAB_];
__device__ __nv_bfloat16 g_w2b[(size_t)LAB_ * LAB_];
__device__ __nv_bfloat16 g_wob[(size_t)LAB_ * V_];      // Wo bf16 [256][32000]
__device__ float g_rowsum[L_];                          // per-row exp sums

// ---------------------------------------------------------------------------
// PTX primitives (sm80-baseline)
// ---------------------------------------------------------------------------
__device__ __forceinline__ uint32_t smem_u32(const void* p) {
    uint32_t a;
    asm("{ .reg .u64 t; cvta.to.shared.u64 t, %1; cvt.u32.u64 %0, t; }"
        : "=r"(a) : "l"(p));
    return a;
}
__device__ __forceinline__ void ldsm_x4(uint32_t r[4], uint32_t addr) {
    asm volatile("ldmatrix.sync.aligned.m8n8.x4.shared.b16 {%0,%1,%2,%3}, [%4];"
        : "=r"(r[0]), "=r"(r[1]), "=r"(r[2]), "=r"(r[3]) : "r"(addr));
}
__device__ __forceinline__ void ldsm_x4_t(uint32_t r[4], uint32_t addr) {
    asm volatile("ldmatrix.sync.aligned.m8n8.x4.trans.shared.b16 {%0,%1,%2,%3}, [%4];"
        : "=r"(r[0]), "=r"(r[1]), "=r"(r[2]), "=r"(r[3]) : "r"(addr));
}
__device__ __forceinline__ void mma_bf16(float d[4], const uint32_t a[4],
                                         uint32_t b0, uint32_t b1) {
    asm volatile(
        "mma.sync.aligned.m16n8k16.row.col.f32.bf16.bf16.f32 "
        "{%0,%1,%2,%3}, {%4,%5,%6,%7}, {%8,%9}, {%0,%1,%2,%3};"
        : "+f"(d[0]), "+f"(d[1]), "+f"(d[2]), "+f"(d[3])
        : "r"(a[0]), "r"(a[1]), "r"(a[2]), "r"(a[3]), "r"(b0), "r"(b1));
}
#define CP_ASYNC16(dst, src) \
    asm volatile("cp.async.cg.shared.global [%0], [%1], 16;" \
        :: "r"(dst), "l"(src) : "memory")
#define CP_COMMIT() asm volatile("cp.async.commit_group;" ::: "memory")
#define CP_WAIT2()  asm volatile("cp.async.wait_group 2;" ::: "memory")
#define CP_WAITALL() asm volatile("cp.async.wait_group 0;" ::: "memory")

__device__ __forceinline__ float ex2f(float x) {
    float r;
    asm("ex2.approx.f32 %0, %1;" : "=f"(r) : "f"(x));
    return r;
}

// ---------------------------------------------------------------------------
// fast exp poly (sigmoid epilogue in wgemm)
// ---------------------------------------------------------------------------
__device__ __forceinline__ float fast_exp(float x) {
    float z = x * 1.4426950408889634f;
    float r = rintf(z);
    float f = z - r;
    float p = 1.3333558146428443e-3f;
    p = fmaf(p, f, 9.6181291976036120e-3f);
    p = fmaf(p, f, 5.5504108664821580e-2f);
    p = fmaf(p, f, 2.4022650695910072e-1f);
    p = fmaf(p, f, 6.9314718055994531e-1f);
    p = fmaf(p, f, 1.0f);
    return __int_as_float(((int)r + 127) << 23) * p;
}

// ---------------------------------------------------------------------------
// span embeddings -> bf16 (float4, 4-way unrolled gather)
// ---------------------------------------------------------------------------
__global__ void span_kernel(const float* __restrict__ hidden,
                            const int* __restrict__ begins,
                            const int* __restrict__ ends,
                            const int* __restrict__ bids) {
    const int l = blockIdx.x;
    const int beg = begins[l];
    const int end = ends[l];
    const int b   = bids[l];
    const float inv_len = 1.0f / (float)(end - beg);
    const float4* hp = (const float4*)hidden;
    const int h4 = threadIdx.x;
    const int H4 = H_ / 4;

    float4 left  = hp[((size_t)(beg - 1) * B_ + b) * H4 + h4];
    float4 right = hp[((size_t)end * B_ + b) * H4 + h4];
    float4 s0 = make_float4(0.f, 0.f, 0.f, 0.f);
    float4 s1 = make_float4(0.f, 0.f, 0.f, 0.f);
    float4 s2 = make_float4(0.f, 0.f, 0.f, 0.f);
    float4 s3 = make_float4(0.f, 0.f, 0.f, 0.f);
    int t = beg;
    for (; t + 4 <= end; t += 4) {
        float4 v0 = hp[((size_t)t * B_ + b) * H4 + h4];
        float4 v1 = hp[((size_t)(t + 1) * B_ + b) * H4 + h4];
        float4 v2 = hp[((size_t)(t + 2) * B_ + b) * H4 + h4];
        float4 v3 = hp[((size_t)(t + 3) * B_ + b) * H4 + h4];
        s0.x += v0.x; s0.y += v0.y; s0.z += v0.z; s0.w += v0.w;
        s1.x += v1.x; s1.y += v1.y; s1.z += v1.z; s1.w += v1.w;
        s2.x += v2.x; s2.y += v2.y; s2.z += v2.z; s2.w += v2.w;
        s3.x += v3.x; s3.y += v3.y; s3.z += v3.z; s3.w += v3.w;
    }
    for (; t < end; ++t) {
        float4 v0 = hp[((size_t)t * B_ + b) * H4 + h4];
        s0.x += v0.x; s0.y += v0.y; s0.z += v0.z; s0.w += v0.w;
    }
    s0.x += s1.x + s2.x + s3.x;
    s0.y += s1.y + s2.y + s3.y;
    s0.z += s1.z + s2.z + s3.z;
    s0.w += s1.w + s2.w + s3.w;

    __nv_bfloat16* out = g_spanb + (size_t)l * (3 * H_);
    uint2 pk;
    pk.x = __nv_bfloat162_raw(__floats2bfloat162_rn(left.x, left.y)).x;
    pk.y = __nv_bfloat162_raw(__floats2bfloat162_rn(left.z, left.w)).x;
    *(uint2*)&out[h4 * 4] = pk;
    pk.x = __nv_bfloat162_raw(__floats2bfloat162_rn(s0.x * inv_len, s0.y * inv_len)).x;
    pk.y = __nv_bfloat162_raw(__floats2bfloat162_rn(s0.z * inv_len, s0.w * inv_len)).x;
    *(uint2*)&out[H_ + h4 * 4] = pk;
    pk.x = __nv_bfloat162_raw(__floats2bfloat162_rn(right.x, right.y)).x;
    pk.y = __nv_bfloat162_raw(__floats2bfloat162_rn(right.z, right.w)).x;
    *(uint2*)&out[2 * H_ + h4 * 4] = pk;
}

// ---------------------------------------------------------------------------
// prep: W1+W2 -> bf16, zero out + g_rowsum (fused launches)
// ---------------------------------------------------------------------------
#define N1_4 (3 * H_ * LAB_ / 4)
#define N2_4 (LAB_ * LAB_ / 4)
__global__ void prep_kernel(const float* __restrict__ W1,
                            const float* __restrict__ W2,
                            float* __restrict__ out) {
    int i = blockIdx.x * blockDim.x + threadIdx.x;
    if (i == 0) out[0] = 0.0f;
    if (i < L_) g_rowsum[i] = 0.0f;
    if (i < N1_4) {
        float4 v = ((const float4*)W1)[i];
        ((__nv_bfloat162*)g_w1b)[2 * i]     = __floats2bfloat162_rn(v.x, v.y);
        ((__nv_bfloat162*)g_w1b)[2 * i + 1] = __floats2bfloat162_rn(v.z, v.w);
    } else if (i < N1_4 + N2_4) {
        int j = i - N1_4;
        float4 v = ((const float4*)W2)[j];
        ((__nv_bfloat162*)g_w2b)[2 * j]     = __floats2bfloat162_rn(v.x, v.y);
        ((__nv_bfloat162*)g_w2b)[2 * j + 1] = __floats2bfloat162_rn(v.z, v.w);
    }
}

// ---------------------------------------------------------------------------
// fp32 -> bf16 conversion (Wo)
// ---------------------------------------------------------------------------
__global__ void cvt_kernel(const float* __restrict__ src,
                           __nv_bfloat16* __restrict__ dst, int n4) {
    int i = blockIdx.x * blockDim.x + threadIdx.x;
    if (i < n4) {
        float4 v = ((const float4*)src)[i];
        ((__nv_bfloat162*)dst)[2 * i]     = __floats2bfloat162_rn(v.x, v.y);
        ((__nv_bfloat162*)dst)[2 * i + 1] = __floats2bfloat162_rn(v.z, v.w);
    }
}

// ---------------------------------------------------------------------------
// wgemm (raw mma.sync): C[M,N] = epi(A[M,K] @ B[K,N] + bias)
// BM=64, BN=64, 128 threads = 4 warps (2x2), warp tile 32x32.
// 4-stage K=64 cp.async ring; direct register epilogue.
// grid (M/64, N/64) = (64, 4) = 256 CTAs.
// ---------------------------------------------------------------------------
template<int K, int EPI>
__global__ __launch_bounds__(128)
void wgemm_kernel(const __nv_bfloat16* __restrict__ A,
                  const __nv_bfloat16* __restrict__ B,
                  const float* __restrict__ bias,
                  float* __restrict__ C32,
                  __nv_bfloat16* __restrict__ Cb, int N) {
    extern __shared__ char smem[];
    const uint32_t sb = smem_u32(smem);

    const int tid = threadIdx.x;
    const int wid = tid >> 5;
    const int lane = tid & 31;
    const int wm = wid >> 1;     // 0..1 (row group of 32)
    const int wn = wid & 1;      // 0..1 (col group of 32)
    const int m0 = blockIdx.x * 64;
    const int n0 = blockIdx.y * 64;
    constexpr int NIT = K / 64;

    auto issue = [&](int g) {
        const int k0 = g * 64;
        const uint32_t st = sb + (g & 3) * WG_STAGE;
        // A: 64 rows x 64 bf16 = 512 x 16B chunks, 4 per thread
#pragma unroll
        for (int i = 0; i < 4; ++i) {
            int c = tid + i * 128;
            int r = c >> 3, kc = c & 7;
            CP_ASYNC16(st + r * WGA_LDB + kc * 16,
                       (const char*)&A[(size_t)(m0 + r) * K + k0 + kc * 8]);
        }
        // B: 64 k-rows x 64 cols = 512 x 16B chunks, 4 per thread
#pragma unroll
        for (int i = 0; i < 4; ++i) {
            int c = tid + i * 128;
            int rk = c >> 3, cc = c & 7;
            CP_ASYNC16(st + WG_A_BYTES + rk * WGB_LDB + cc * 16,
                       (const char*)&B[(size_t)(k0 + rk) * N + n0 + cc * 8]);
        }
    };

    uint32_t aBase[2];
#pragma unroll
    for (int mi = 0; mi < 2; ++mi)
        aBase[mi] = sb + (wm * 32 + mi * 16 + (lane & 15)) * WGA_LDB
                  + (lane >> 4) * 16;
    uint32_t bBase[2];
#pragma unroll
    for (int ng = 0; ng < 2; ++ng)
        bBase[ng] = sb + WG_A_BYTES + (lane & 15) * WGB_LDB
                  + (wn * 32 + ng * 16) * 2 + (lane >> 4) * 16;

    float acc[2][4][4];
#pragma unroll
    for (int mi = 0; mi < 2; ++mi)
#pragma unroll
        for (int ni = 0; ni < 4; ++ni)
#pragma unroll
            for (int j = 0; j < 4; ++j) acc[mi][ni][j] = 0.0f;

#pragma unroll
    for (int st = 0; st < 3 && st < NIT; ++st) { issue(st); CP_COMMIT(); }
#pragma unroll
    for (int st = NIT; st < 3; ++st) CP_COMMIT();   // keep group count exact

    for (int g = 0; g < NIT; ++g) {
        CP_WAIT2();
        __syncthreads();
        if (g + 3 < NIT) issue(g + 3);
        CP_COMMIT();
        const uint32_t stOff = (g & 3) * WG_STAGE;
#pragma unroll
        for (int s = 0; s < 4; ++s) {    // 4 k16 substeps per K=64 stage
            uint32_t a[2][4], bb[2][4];
#pragma unroll
            for (int mi = 0; mi < 2; ++mi)
                ldsm_x4(a[mi], aBase[mi] + stOff + s * 32);
#pragma unroll
            for (int ng = 0; ng < 2; ++ng)
                ldsm_x4_t(bb[ng], bBase[ng] + stOff + s * 16 * WGB_LDB);
#pragma unroll
            for (int mi = 0; mi < 2; ++mi)
#pragma unroll
                for (int ni = 0; ni < 4; ++ni)
                    mma_bf16(acc[mi][ni], a[mi],
                             bb[ni >> 1][(ni & 1) * 2],
                             bb[ni >> 1][(ni & 1) * 2 + 1]);
        }
        __syncthreads();
    }
    CP_WAITALL();

    // direct register epilogue (m16n8k16 acc lane mapping)
#pragma unroll
    for (int mi = 0; mi < 2; ++mi) {
        const int r0 = m0 + wm * 32 + mi * 16 + (lane >> 2);
#pragma unroll
        for (int ni = 0; ni < 4; ++ni) {
            const int gc = n0 + wn * 32 + ni * 8 + (lane & 3) * 2;
            float2 bv = *(const float2*)&bias[gc];
            float v00 = acc[mi][ni][0] + bv.x;
            float v01 = acc[mi][ni][1] + bv.y;
            float v10 = acc[mi][ni][2] + bv.x;
            float v11 = acc[mi][ni][3] + bv.y;
            if (EPI == 1) {
                v00 = 1.0f / (1.0f + fast_exp(-v00));
                v01 = 1.0f / (1.0f + fast_exp(-v01));
                v10 = 1.0f / (1.0f + fast_exp(-v10));
                v11 = 1.0f / (1.0f + fast_exp(-v11));
                *(__nv_bfloat162*)&Cb[(size_t)r0 * N + gc] =
                    __floats2bfloat162_rn(v00, v01);
                *(__nv_bfloat162*)&Cb[(size_t)(r0 + 8) * N + gc] =
                    __floats2bfloat162_rn(v10, v11);
            } else {
                *(float2*)&C32[(size_t)r0 * N + gc] = make_float2(v00, v01);
                *(float2*)&C32[(size_t)(r0 + 8) * N + gc] = make_float2(v10, v11);
                *(__nv_bfloat162*)&Cb[(size_t)r0 * N + gc] =
                    __floats2bfloat162_rn(v00, v01);
                *(__nv_bfloat162*)&Cb[(size_t)(r0 + 8) * N + gc] =
                    __floats2bfloat162_rn(v10, v11);
            }
        }
    }
}

// ---------------------------------------------------------------------------
// cls: PERSISTENT mma.sync bf16 classifier GEMM + fused per-row exp-sums.
// 128 threads = 4 warps, 2x2 grid of 64x64 warp tiles (R14 exact config).
// grid = 296 (2 CTAs/SM). Work = 8000 items (rb, vtile), rowblock-major.
// ---------------------------------------------------------------------------
__global__ __launch_bounds__(128, 2)
void cls_kernel(const float* __restrict__ bo) {
    extern __shared__ char smem[];
    const uint32_t sb = smem_u32(smem);

    const int tid = threadIdx.x;
    const int wid = tid >> 5;
    const int lane = tid & 31;
    const int wm = wid >> 1;          // 0..1 (row group of 64)
    const int wn = wid & 1;           // 0..1 (col group of 64)
    const float LOG2E = 1.4426950408889634f;

    const int start = (blockIdx.x * N_ITEMS) / CLS_GRID;
    const int end   = ((blockIdx.x + 1) * N_ITEMS) / CLS_GRID;
    const int NST   = (end - start) * 8;

    uint32_t aBase[4];
#pragma unroll
    for (int mi = 0; mi < 4; ++mi)
        aBase[mi] = sb + CLS_A_OFF
                  + (wm * 64 + mi * 16 + (lane & 15)) * AS_LDB
                  + (lane >> 4) * 16;
    uint32_t bBase[4];
#pragma unroll
    for (int ng = 0; ng < 4; ++ng)
        bBase[ng] = sb + CLS_B_OFF + (lane & 15) * BS_LDB
                  + (wn * 64 + ng * 16) * 2 + (lane >> 4) * 16;

    auto issue_stage = [&](int gs) {
        const int item = start + (gs >> 3);
        const int k0 = (gs & 7) * 32;
        const int v0 = (item % N_VT) * CLS_BN;
        const uint32_t dbase = sb + CLS_B_OFF + (gs & 3) * CLS_B_TILE;
#pragma unroll
        for (int i = 0; i < 4; ++i) {
            int c = tid + i * 128;
            int row = c >> 4, col = c & 15;
            CP_ASYNC16(dbase + row * BS_LDB + col * 16,
                       (const char*)(g_wob + (size_t)(k0 + row) * V_
                                     + v0 + col * 8));
        }
    };

#pragma unroll
    for (int st = 0; st < 3; ++st) { issue_stage(st); CP_COMMIT(); }

    float rAcc[4][2];
#pragma unroll
    for (int mi = 0; mi < 4; ++mi) { rAcc[mi][0] = 0.f; rAcc[mi][1] = 0.f; }

    float acc[4][8][4];
#pragma unroll
    for (int mi = 0; mi < 4; ++mi)
#pragma unroll
        for (int ni = 0; ni < 8; ++ni)
#pragma unroll
            for (int j = 0; j < 4; ++j) acc[mi][ni][j] = 0.0f;

    int cur_rb = -1;

    auto flush = [&](int rb) {
#pragma unroll
        for (int mi = 0; mi < 4; ++mi)
#pragma unroll
            for (int hi = 0; hi < 2; ++hi) {
                float v = rAcc[mi][hi];
                v += __shfl_xor_sync(0xFFFFFFFFu, v, 1);
                v += __shfl_xor_sync(0xFFFFFFFFu, v, 2);
                if ((lane & 3) == 0)
                    atomicAdd(&g_rowsum[rb * CLS_BM + wm * 64 + mi * 16
                                        + hi * 8 + (lane >> 2)], v);
                rAcc[mi][hi] = 0.0f;
            }
    };

    for (int gs = 0; gs < NST; ++gs) {
        CP_WAIT2();
        __syncthreads();
        if (gs + 3 < NST) issue_stage(gs + 3);
        CP_COMMIT();

        const int item = start + (gs >> 3);
        if ((gs & 7) == 0) {
            const int rb = item / N_VT;
            if (rb != cur_rb) {
                if (cur_rb >= 0) flush(cur_rb);
                const __nv_bfloat16* src = g_featb + (size_t)rb * CLS_BM * LAB_;
#pragma unroll
                for (int t = tid; t < CLS_BM * 32; t += 128) {
                    int r = t >> 5, k8 = t & 31;
                    uint4 v = *(const uint4*)&src[(size_t)r * LAB_ + k8 * 8];
                    *(uint4*)(smem + CLS_A_OFF + r * AS_LDB + k8 * 16) = v;
                }
                __syncthreads();
                cur_rb = rb;
            }
        }

        const uint32_t bufOff = (gs & 3) * CLS_B_TILE;
        const uint32_t aOff = (gs & 7) * 64;
#pragma unroll
        for (int s = 0; s < 2; ++s) {
            uint32_t a[4][4], bb[4][4];
#pragma unroll
            for (int mi = 0; mi < 4; ++mi)
                ldsm_x4(a[mi], aBase[mi] + aOff + s * 32);
#pragma unroll
            for (int ng = 0; ng < 4; ++ng)
                ldsm_x4_t(bb[ng], bBase[ng] + bufOff + s * 16 * BS_LDB);
#pragma unroll
            for (int mi = 0; mi < 4; ++mi)
#pragma unroll
                for (int ni = 0; ni < 8; ++ni)
                    mma_bf16(acc[mi][ni], a[mi],
                             bb[ni >> 1][(ni & 1) * 2],
                             bb[ni >> 1][(ni & 1) * 2 + 1]);
        }

        if ((gs & 7) == 7) {
            const int v0 = (item % N_VT) * CLS_BN;
            const float* bop = bo + v0 + wn * 64 + (lane & 3) * 2;
#pragma unroll
            for (int ni = 0; ni < 8; ++ni) {
                float2 bv = *(const float2*)(bop + ni * 8);
                float b0 = bv.x * LOG2E, b1 = bv.y * LOG2E;
#pragma unroll
                for (int mi = 0; mi < 4; ++mi) {
                    rAcc[mi][0] += ex2f(fmaf(acc[mi][ni][0], LOG2E, b0))
                                 + ex2f(fmaf(acc[mi][ni][1], LOG2E, b1));
                    rAcc[mi][1] += ex2f(fmaf(acc[mi][ni][2], LOG2E, b0))
                                 + ex2f(fmaf(acc[mi][ni][3], LOG2E, b1));
                    acc[mi][ni][0] = 0.f; acc[mi][ni][1] = 0.f;
                    acc[mi][ni][2] = 0.f; acc[mi][ni][3] = 0.f;
                }
            }
        }
    }
    CP_WAITALL();
    if (cur_rb >= 0) flush(cur_rb);
}

// ---------------------------------------------------------------------------
// loss: per-row fp32 tag logit + log(rowsum) + global sum
// ---------------------------------------------------------------------------
__global__ void loss_kernel(const float* __restrict__ Wo,
                            const float* __restrict__ bo,
                            const int* __restrict__ tags,
                            float* __restrict__ out) {
    const int warp = (blockIdx.x * blockDim.x + threadIdx.x) >> 5;
    const int lane = threadIdx.x & 31;
    const int nwarps = (gridDim.x * blockDim.x) >> 5;
    float local = 0.0f;
    for (int l = warp; l < L_; l += nwarps) {
        int tag = tags[l];
        float dot = 0.0f;
#pragma unroll
        for (int j = 0; j < 8; ++j) {
            int k = lane + j * 32;
            dot += g_feat[(size_t)l * 256 + k] * Wo[(size_t)k * V_ + tag];
        }
#pragma unroll
        for (int off = 16; off > 0; off >>= 1)
            dot += __shfl_down_sync(0xFFFFFFFFu, dot, off);
        if (lane == 0)
            local += logf(g_rowsum[l]) - (dot + bo[tag]);
    }
    if (lane == 0)
        atomicAdd(out, local * (1.0f / (4096.0f + 1e-5f)));
}

// ---------------------------------------------------------------------------
// Launch. Inputs: hidden, begins, ends, bids, tags, W1, b1, W2, b2, Wo, bo
// ---------------------------------------------------------------------------
extern "C" void kernel_launch(void* const* d_in, const int* in_sizes, int n_in,
                              void* d_out, int out_size) {
    const float* hidden = (const float*)d_in[0];
    const int*   begins = (const int*)d_in[1];
    const int*   ends   = (const int*)d_in[2];
    const int*   bids   = (const int*)d_in[3];
    const int*   tags   = (const int*)d_in[4];
    const float* W1     = (const float*)d_in[5];
    const float* b1     = (const float*)d_in[6];
    const float* W2     = (const float*)d_in[7];
    const float* b2     = (const float*)d_in[8];
    const float* Wo     = (const float*)d_in[9];
    const float* bo     = (const float*)d_in[10];
    float* out = (float*)d_out;

    __nv_bfloat16 *spanb, *h1b, *featb, *w1b, *w2b, *wob;
    float* feat;
    cudaGetSymbolAddress((void**)&spanb, g_spanb);
    cudaGetSymbolAddress((void**)&h1b, g_h1b);
    cudaGetSymbolAddress((void**)&feat, g_feat);
    cudaGetSymbolAddress((void**)&featb, g_featb);
    cudaGetSymbolAddress((void**)&w1b, g_w1b);
    cudaGetSymbolAddress((void**)&w2b, g_w2b);
    cudaGetSymbolAddress((void**)&wob, g_wob);

    // opt-in dynamic smem (all kernels over the 48KB default)
    cudaFuncSetAttribute(wgemm_kernel<3 * H_, 1>,
                         cudaFuncAttributeMaxDynamicSharedMemorySize,
                         WG_SMEM_BYTES);
    cudaFuncSetAttribute(wgemm_kernel<LAB_, 2>,
                         cudaFuncAttributeMaxDynamicSharedMemorySize,
                         WG_SMEM_BYTES);
    cudaFuncSetAttribute(cls_kernel,
                         cudaFuncAttributeMaxDynamicSharedMemorySize,
                         CLS_SMEM);

    // weight prep (bf16) + zero out + zero rowsums
    prep_kernel<<<(N1_4 + N2_4 + 255) / 256, 256>>>(W1, W2, out);
    cvt_kernel<<<(LAB_ * V_ / 4 + 255) / 256, 256>>>(Wo, wob, LAB_ * V_ / 4);

    // 1) span embeddings (bf16)
    span_kernel<<<L_, 128>>>(hidden, begins, ends, bids);

    // 2) h1 = sigmoid(span @ W1 + b1) -> bf16
    {
        dim3 grid(L_ / 64, LAB_ / 64);
        wgemm_kernel<3 * H_, 1><<<grid, 128, WG_SMEM_BYTES>>>(
            spanb, w1b, b1, nullptr, h1b, LAB_);
    }
    // 3) feat = h1 @ W2 + b2 -> fp32 + bf16
    {
        dim3 grid(L_ / 64, LAB_ / 64);
        wgemm_kernel<LAB_, 2><<<grid, 128, WG_SMEM_BYTES>>>(
            h1b, w2b, b2, feat, featb, LAB_);
    }
    // 4) persistent mma.sync classifier GEMM + fused exp-sum
    cls_kernel<<<CLS_GRID, 128, CLS_SMEM>>>(bo);

    // 5) final loss reduction
    loss_kernel<<<32, 256>>>(Wo, bo, tags, out);
}

// round 17
// speedup vs baseline: 1.1113x; 1.0136x over previous
#include <cuda_runtime.h>
#include <cuda_bf16.h>
#include <math.h>
#include <stdint.h>

// Problem constants
#define S_    2048
#define B_    16
#define H_    512
#define L_    4096
#define LAB_  256
#define V_    32000

// cls: persistent grid, rowblock-major work items, 128 threads (4 warps 2x2)
#define CLS_BM    128
#define CLS_BN    128
#define CLS_GRID  296                 // 2 CTAs x 148 SMs, one wave
#define N_RB      (L_ / CLS_BM)       // 32 rowblocks
#define N_VT      (V_ / CLS_BN)       // 250 v-tiles
#define N_ITEMS   (N_RB * N_VT)       // 8000

// cls smem (bytes)
#define AS_LDB   528
#define BS_LDB   272
#define CLS_A_OFF 0
#define CLS_A_BYTES (CLS_BM * AS_LDB)        // 67584
#define CLS_B_OFF  CLS_A_BYTES
#define CLS_B_TILE (32 * BS_LDB)             // 8704
#define CLS_B_BYTES (4 * CLS_B_TILE)         // 34816
#define CLS_SMEM (CLS_B_OFF + CLS_B_BYTES)   // 102400 -> 2 CTAs/SM

// wgemm (raw mma): BM=64, BN=64, 128 threads, K=64 stages, 4-stage ring
#define WGA_LDB 144
#define WGB_LDB 144
#define WG_A_BYTES (64 * WGA_LDB)            // 9216
#define WG_STAGE (WG_A_BYTES + 64 * WGB_LDB) // 18432
#define WG_SMEM_BYTES (4 * WG_STAGE)         // 73728

// Scratch
__device__ __nv_bfloat16 g_spanb[(size_t)L_ * 3 * H_];
__device__ __nv_bfloat16 g_h1b[(size_t)L_ * LAB_];
__device__ float g_feat[(size_t)L_ * LAB_];
__device__ __nv_bfloat16 g_featb[(size_t)L_ * LAB_];
__device__ __nv_bfloat16 g_w1b[(size_t)3 * H_ * LAB_];
__device__ __nv_bfloat16 g_w2b[(size_t)LAB_ * LAB_];
__device__ __nv_bfloat16 g_wob[(size_t)LAB_ * V_];
__device__ float g_rowsum[L_];

// ---------------------------------------------------------------------------
// PTX primitives
// ---------------------------------------------------------------------------
__device__ __forceinline__ uint32_t smem_u32(const void* p) {
    uint32_t a;
    asm("{ .reg .u64 t; cvta.to.shared.u64 t, %1; cvt.u32.u64 %0, t; }"
        : "=r"(a) : "l"(p));
    return a;
}
__device__ __forceinline__ void ldsm_x4(uint32_t r[4], uint32_t addr) {
    asm volatile("ldmatrix.sync.aligned.m8n8.x4.shared.b16 {%0,%1,%2,%3}, [%4];"
        : "=r"(r[0]), "=r"(r[1]), "=r"(r[2]), "=r"(r[3]) : "r"(addr));
}
__device__ __forceinline__ void ldsm_x4_t(uint32_t r[4], uint32_t addr) {
    asm volatile("ldmatrix.sync.aligned.m8n8.x4.trans.shared.b16 {%0,%1,%2,%3}, [%4];"
        : "=r"(r[0]), "=r"(r[1]), "=r"(r[2]), "=r"(r[3]) : "r"(addr));
}
__device__ __forceinline__ void mma_bf16(float d[4], const uint32_t a[4],
                                         uint32_t b0, uint32_t b1) {
    asm volatile(
        "mma.sync.aligned.m16n8k16.row.col.f32.bf16.bf16.f32 "
        "{%0,%1,%2,%3}, {%4,%5,%6,%7}, {%8,%9}, {%0,%1,%2,%3};"
        : "+f"(d[0]), "+f"(d[1]), "+f"(d[2]), "+f"(d[3])
        : "r"(a[0]), "r"(a[1]), "r"(a[2]), "r"(a[3]), "r"(b0), "r"(b1));
}
#define CP_ASYNC16(dst, src) \
    asm volatile("cp.async.cg.shared.global [%0], [%1], 16;" \
        :: "r"(dst), "l"(src) : "memory")
#define CP_COMMIT() asm volatile("cp.async.commit_group;" ::: "memory")
#define CP_WAIT2()  asm volatile("cp.async.wait_group 2;" ::: "memory")
#define CP_WAITALL() asm volatile("cp.async.wait_group 0;" ::: "memory")

__device__ __forceinline__ float ex2f(float x) {
    float r;
    asm("ex2.approx.f32 %0, %1;" : "=f"(r) : "f"(x));
    return r;
}

// ---------------------------------------------------------------------------
__device__ __forceinline__ float fast_exp(float x) {
    float z = x * 1.4426950408889634f;
    float r = rintf(z);
    float f = z - r;
    float p = 1.3333558146428443e-3f;
    p = fmaf(p, f, 9.6181291976036120e-3f);
    p = fmaf(p, f, 5.5504108664821580e-2f);
    p = fmaf(p, f, 2.4022650695910072e-1f);
    p = fmaf(p, f, 6.9314718055994531e-1f);
    p = fmaf(p, f, 1.0f);
    return __int_as_float(((int)r + 127) << 23) * p;
}

// ---------------------------------------------------------------------------
// span embeddings -> bf16
// ---------------------------------------------------------------------------
__global__ void span_kernel(const float* __restrict__ hidden,
                            const int* __restrict__ begins,
                            const int* __restrict__ ends,
                            const int* __restrict__ bids) {
    const int l = blockIdx.x;
    const int beg = begins[l];
    const int end = ends[l];
    const int b   = bids[l];
    const float inv_len = 1.0f / (float)(end - beg);
    const float4* hp = (const float4*)hidden;
    const int h4 = threadIdx.x;
    const int H4 = H_ / 4;

    float4 left  = hp[((size_t)(beg - 1) * B_ + b) * H4 + h4];
    float4 right = hp[((size_t)end * B_ + b) * H4 + h4];
    float4 s0 = make_float4(0.f, 0.f, 0.f, 0.f);
    float4 s1 = make_float4(0.f, 0.f, 0.f, 0.f);
    float4 s2 = make_float4(0.f, 0.f, 0.f, 0.f);
    float4 s3 = make_float4(0.f, 0.f, 0.f, 0.f);
    int t = beg;
    for (; t + 4 <= end; t += 4) {
        float4 v0 = hp[((size_t)t * B_ + b) * H4 + h4];
        float4 v1 = hp[((size_t)(t + 1) * B_ + b) * H4 + h4];
        float4 v2 = hp[((size_t)(t + 2) * B_ + b) * H4 + h4];
        float4 v3 = hp[((size_t)(t + 3) * B_ + b) * H4 + h4];
        s0.x += v0.x; s0.y += v0.y; s0.z += v0.z; s0.w += v0.w;
        s1.x += v1.x; s1.y += v1.y; s1.z += v1.z; s1.w += v1.w;
        s2.x += v2.x; s2.y += v2.y; s2.z += v2.z; s2.w += v2.w;
        s3.x += v3.x; s3.y += v3.y; s3.z += v3.z; s3.w += v3.w;
    }
    for (; t < end; ++t) {
        float4 v0 = hp[((size_t)t * B_ + b) * H4 + h4];
        s0.x += v0.x; s0.y += v0.y; s0.z += v0.z; s0.w += v0.w;
    }
    s0.x += s1.x + s2.x + s3.x;
    s0.y += s1.y + s2.y + s3.y;
    s0.z += s1.z + s2.z + s3.z;
    s0.w += s1.w + s2.w + s3.w;

    __nv_bfloat16* out = g_spanb + (size_t)l * (3 * H_);
    uint2 pk;
    pk.x = __nv_bfloat162_raw(__floats2bfloat162_rn(left.x, left.y)).x;
    pk.y = __nv_bfloat162_raw(__floats2bfloat162_rn(left.z, left.w)).x;
    *(uint2*)&out[h4 * 4] = pk;
    pk.x = __nv_bfloat162_raw(__floats2bfloat162_rn(s0.x * inv_len, s0.y * inv_len)).x;
    pk.y = __nv_bfloat162_raw(__floats2bfloat162_rn(s0.z * inv_len, s0.w * inv_len)).x;
    *(uint2*)&out[H_ + h4 * 4] = pk;
    pk.x = __nv_bfloat162_raw(__floats2bfloat162_rn(right.x, right.y)).x;
    pk.y = __nv_bfloat162_raw(__floats2bfloat162_rn(right.z, right.w)).x;
    *(uint2*)&out[2 * H_ + h4 * 4] = pk;
}

// ---------------------------------------------------------------------------
// prep: W1+W2 -> bf16, zero out + g_rowsum
// ---------------------------------------------------------------------------
#define N1_4 (3 * H_ * LAB_ / 4)
#define N2_4 (LAB_ * LAB_ / 4)
__global__ void prep_kernel(const float* __restrict__ W1,
                            const float* __restrict__ W2,
                            float* __restrict__ out) {
    int i = blockIdx.x * blockDim.x + threadIdx.x;
    if (i == 0) out[0] = 0.0f;
    if (i < L_) g_rowsum[i] = 0.0f;
    if (i < N1_4) {
        float4 v = ((const float4*)W1)[i];
        ((__nv_bfloat162*)g_w1b)[2 * i]     = __floats2bfloat162_rn(v.x, v.y);
        ((__nv_bfloat162*)g_w1b)[2 * i + 1] = __floats2bfloat162_rn(v.z, v.w);
    } else if (i < N1_4 + N2_4) {
        int j = i - N1_4;
        float4 v = ((const float4*)W2)[j];
        ((__nv_bfloat162*)g_w2b)[2 * j]     = __floats2bfloat162_rn(v.x, v.y);
        ((__nv_bfloat162*)g_w2b)[2 * j + 1] = __floats2bfloat162_rn(v.z, v.w);
    }
}

// ---------------------------------------------------------------------------
// fp32 -> bf16 (Wo)
// ---------------------------------------------------------------------------
__global__ void cvt_kernel(const float* __restrict__ src,
                           __nv_bfloat16* __restrict__ dst, int n4) {
    int i = blockIdx.x * blockDim.x + threadIdx.x;
    if (i < n4) {
        float4 v = ((const float4*)src)[i];
        ((__nv_bfloat162*)dst)[2 * i]     = __floats2bfloat162_rn(v.x, v.y);
        ((__nv_bfloat162*)dst)[2 * i + 1] = __floats2bfloat162_rn(v.z, v.w);
    }
}

// ---------------------------------------------------------------------------
// wgemm (raw mma.sync): BM=64, BN=64, 128 threads, K=64 stages, 4-stage ring.
// Fragment-level pipelining: all 16 ldsm for the stage issued back-to-back,
// then 32 dependency-free mma.
// ---------------------------------------------------------------------------
template<int K, int EPI>
__global__ __launch_bounds__(128)
void wgemm_kernel(const __nv_bfloat16* __restrict__ A,
                  const __nv_bfloat16* __restrict__ B,
                  const float* __restrict__ bias,
                  float* __restrict__ C32,
                  __nv_bfloat16* __restrict__ Cb, int N) {
    extern __shared__ char smem[];
    const uint32_t sb = smem_u32(smem);

    const int tid = threadIdx.x;
    const int wid = tid >> 5;
    const int lane = tid & 31;
    const int wm = wid >> 1;
    const int wn = wid & 1;
    const int m0 = blockIdx.x * 64;
    const int n0 = blockIdx.y * 64;
    constexpr int NIT = K / 64;

    auto issue = [&](int g) {
        const int k0 = g * 64;
        const uint32_t st = sb + (g & 3) * WG_STAGE;
#pragma unroll
        for (int i = 0; i < 4; ++i) {
            int c = tid + i * 128;
            int r = c >> 3, kc = c & 7;
            CP_ASYNC16(st + r * WGA_LDB + kc * 16,
                       (const char*)&A[(size_t)(m0 + r) * K + k0 + kc * 8]);
        }
#pragma unroll
        for (int i = 0; i < 4; ++i) {
            int c = tid + i * 128;
            int rk = c >> 3, cc = c & 7;
            CP_ASYNC16(st + WG_A_BYTES + rk * WGB_LDB + cc * 16,
                       (const char*)&B[(size_t)(k0 + rk) * N + n0 + cc * 8]);
        }
    };

    uint32_t aBase[2];
#pragma unroll
    for (int mi = 0; mi < 2; ++mi)
        aBase[mi] = sb + (wm * 32 + mi * 16 + (lane & 15)) * WGA_LDB
                  + (lane >> 4) * 16;
    uint32_t bBase[2];
#pragma unroll
    for (int ng = 0; ng < 2; ++ng)
        bBase[ng] = sb + WG_A_BYTES + (lane & 15) * WGB_LDB
                  + (wn * 32 + ng * 16) * 2 + (lane >> 4) * 16;

    float acc[2][4][4];
#pragma unroll
    for (int mi = 0; mi < 2; ++mi)
#pragma unroll
        for (int ni = 0; ni < 4; ++ni)
#pragma unroll
            for (int j = 0; j < 4; ++j) acc[mi][ni][j] = 0.0f;

#pragma unroll
    for (int st = 0; st < 3 && st < NIT; ++st) { issue(st); CP_COMMIT(); }
#pragma unroll
    for (int st = NIT; st < 3; ++st) CP_COMMIT();

    for (int g = 0; g < NIT; ++g) {
        CP_WAIT2();
        __syncthreads();
        if (g + 3 < NIT) issue(g + 3);
        CP_COMMIT();
        const uint32_t stOff = (g & 3) * WG_STAGE;
        // load all fragments for 4 k16 substeps
        uint32_t a[4][2][4], bb[4][2][4];
#pragma unroll
        for (int s = 0; s < 4; ++s)
#pragma unroll
            for (int mi = 0; mi < 2; ++mi)
                ldsm_x4(a[s][mi], aBase[mi] + stOff + s * 32);
#pragma unroll
        for (int s = 0; s < 4; ++s)
#pragma unroll
            for (int ng = 0; ng < 2; ++ng)
                ldsm_x4_t(bb[s][ng], bBase[ng] + stOff + s * 16 * WGB_LDB);
        // all mma
#pragma unroll
        for (int s = 0; s < 4; ++s)
#pragma unroll
            for (int mi = 0; mi < 2; ++mi)
#pragma unroll
                for (int ni = 0; ni < 4; ++ni)
                    mma_bf16(acc[mi][ni], a[s][mi],
                             bb[s][ni >> 1][(ni & 1) * 2],
                             bb[s][ni >> 1][(ni & 1) * 2 + 1]);
        __syncthreads();
    }
    CP_WAITALL();

#pragma unroll
    for (int mi = 0; mi < 2; ++mi) {
        const int r0 = m0 + wm * 32 + mi * 16 + (lane >> 2);
#pragma unroll
        for (int ni = 0; ni < 4; ++ni) {
            const int gc = n0 + wn * 32 + ni * 8 + (lane & 3) * 2;
            float2 bv = *(const float2*)&bias[gc];
            float v00 = acc[mi][ni][0] + bv.x;
            float v01 = acc[mi][ni][1] + bv.y;
            float v10 = acc[mi][ni][2] + bv.x;
            float v11 = acc[mi][ni][3] + bv.y;
            if (EPI == 1) {
                v00 = 1.0f / (1.0f + fast_exp(-v00));
                v01 = 1.0f / (1.0f + fast_exp(-v01));
                v10 = 1.0f / (1.0f + fast_exp(-v10));
                v11 = 1.0f / (1.0f + fast_exp(-v11));
                *(__nv_bfloat162*)&Cb[(size_t)r0 * N + gc] =
                    __floats2bfloat162_rn(v00, v01);
                *(__nv_bfloat162*)&Cb[(size_t)(r0 + 8) * N + gc] =
                    __floats2bfloat162_rn(v10, v11);
            } else {
                *(float2*)&C32[(size_t)r0 * N + gc] = make_float2(v00, v01);
                *(float2*)&C32[(size_t)(r0 + 8) * N + gc] = make_float2(v10, v11);
                *(__nv_bfloat162*)&Cb[(size_t)r0 * N + gc] =
                    __floats2bfloat162_rn(v00, v01);
                *(__nv_bfloat162*)&Cb[(size_t)(r0 + 8) * N + gc] =
                    __floats2bfloat162_rn(v10, v11);
            }
        }
    }
}

// ---------------------------------------------------------------------------
// cls: PERSISTENT mma.sync bf16 classifier GEMM + fused per-row exp-sums.
// Fragment-level pipelining: all 16 ldsm for the K=32 stage, then 64 mma.
// ---------------------------------------------------------------------------
__global__ __launch_bounds__(128, 2)
void cls_kernel(const float* __restrict__ bo) {
    extern __shared__ char smem[];
    const uint32_t sb = smem_u32(smem);

    const int tid = threadIdx.x;
    const int wid = tid >> 5;
    const int lane = tid & 31;
    const int wm = wid >> 1;
    const int wn = wid & 1;
    const float LOG2E = 1.4426950408889634f;

    const int start = (blockIdx.x * N_ITEMS) / CLS_GRID;
    const int end   = ((blockIdx.x + 1) * N_ITEMS) / CLS_GRID;
    const int NST   = (end - start) * 8;

    uint32_t aBase[4];
#pragma unroll
    for (int mi = 0; mi < 4; ++mi)
        aBase[mi] = sb + CLS_A_OFF
                  + (wm * 64 + mi * 16 + (lane & 15)) * AS_LDB
                  + (lane >> 4) * 16;
    uint32_t bBase[4];
#pragma unroll
    for (int ng = 0; ng < 4; ++ng)
        bBase[ng] = sb + CLS_B_OFF + (lane & 15) * BS_LDB
                  + (wn * 64 + ng * 16) * 2 + (lane >> 4) * 16;

    auto issue_stage = [&](int gs) {
        const int item = start + (gs >> 3);
        const int k0 = (gs & 7) * 32;
        const int v0 = (item % N_VT) * CLS_BN;
        const uint32_t dbase = sb + CLS_B_OFF + (gs & 3) * CLS_B_TILE;
#pragma unroll
        for (int i = 0; i < 4; ++i) {
            int c = tid + i * 128;
            int row = c >> 4, col = c & 15;
            CP_ASYNC16(dbase + row * BS_LDB + col * 16,
                       (const char*)(g_wob + (size_t)(k0 + row) * V_
                                     + v0 + col * 8));
        }
    };

#pragma unroll
    for (int st = 0; st < 3; ++st) { issue_stage(st); CP_COMMIT(); }

    float rAcc[4][2];
#pragma unroll
    for (int mi = 0; mi < 4; ++mi) { rAcc[mi][0] = 0.f; rAcc[mi][1] = 0.f; }

    float acc[4][8][4];
#pragma unroll
    for (int mi = 0; mi < 4; ++mi)
#pragma unroll
        for (int ni = 0; ni < 8; ++ni)
#pragma unroll
            for (int j = 0; j < 4; ++j) acc[mi][ni][j] = 0.0f;

    int cur_rb = -1;

    auto flush = [&](int rb) {
#pragma unroll
        for (int mi = 0; mi < 4; ++mi)
#pragma unroll
            for (int hi = 0; hi < 2; ++hi) {
                float v = rAcc[mi][hi];
                v += __shfl_xor_sync(0xFFFFFFFFu, v, 1);
                v += __shfl_xor_sync(0xFFFFFFFFu, v, 2);
                if ((lane & 3) == 0)
                    atomicAdd(&g_rowsum[rb * CLS_BM + wm * 64 + mi * 16
                                        + hi * 8 + (lane >> 2)], v);
                rAcc[mi][hi] = 0.0f;
            }
    };

    for (int gs = 0; gs < NST; ++gs) {
        CP_WAIT2();
        __syncthreads();
        if (gs + 3 < NST) issue_stage(gs + 3);
        CP_COMMIT();

        const int item = start + (gs >> 3);
        if ((gs & 7) == 0) {
            const int rb = item / N_VT;
            if (rb != cur_rb) {
                if (cur_rb >= 0) flush(cur_rb);
                const __nv_bfloat16* src = g_featb + (size_t)rb * CLS_BM * LAB_;
#pragma unroll
                for (int t = tid; t < CLS_BM * 32; t += 128) {
                    int r = t >> 5, k8 = t & 31;
                    uint4 v = *(const uint4*)&src[(size_t)r * LAB_ + k8 * 8];
                    *(uint4*)(smem + CLS_A_OFF + r * AS_LDB + k8 * 16) = v;
                }
                __syncthreads();
                cur_rb = rb;
            }
        }

        const uint32_t bufOff = (gs & 3) * CLS_B_TILE;
        const uint32_t aOff = (gs & 7) * 64;
        // load all fragments for both k16 substeps (16 ldsm back-to-back)
        uint32_t a[2][4][4], bb[2][4][4];
#pragma unroll
        for (int s = 0; s < 2; ++s)
#pragma unroll
            for (int mi = 0; mi < 4; ++mi)
                ldsm_x4(a[s][mi], aBase[mi] + aOff + s * 32);
#pragma unroll
        for (int s = 0; s < 2; ++s)
#pragma unroll
            for (int ng = 0; ng < 4; ++ng)
                ldsm_x4_t(bb[s][ng], bBase[ng] + bufOff + s * 16 * BS_LDB);
        // all 64 mma dependency-free
#pragma unroll
        for (int s = 0; s < 2; ++s)
#pragma unroll
            for (int mi = 0; mi < 4; ++mi)
#pragma unroll
                for (int ni = 0; ni < 8; ++ni)
                    mma_bf16(acc[mi][ni], a[s][mi],
                             bb[s][ni >> 1][(ni & 1) * 2],
                             bb[s][ni >> 1][(ni & 1) * 2 + 1]);

        if ((gs & 7) == 7) {
            const int v0 = (item % N_VT) * CLS_BN;
            const float* bop = bo + v0 + wn * 64 + (lane & 3) * 2;
#pragma unroll
            for (int ni = 0; ni < 8; ++ni) {
                float2 bv = *(const float2*)(bop + ni * 8);
                float b0 = bv.x * LOG2E, b1 = bv.y * LOG2E;
#pragma unroll
                for (int mi = 0; mi < 4; ++mi) {
                    rAcc[mi][0] += ex2f(fmaf(acc[mi][ni][0], LOG2E, b0))
                                 + ex2f(fmaf(acc[mi][ni][1], LOG2E, b1));
                    rAcc[mi][1] += ex2f(fmaf(acc[mi][ni][2], LOG2E, b0))
                                 + ex2f(fmaf(acc[mi][ni][3], LOG2E, b1));
                    acc[mi][ni][0] = 0.f; acc[mi][ni][1] = 0.f;
                    acc[mi][ni][2] = 0.f; acc[mi][ni][3] = 0.f;
                }
            }
        }
    }
    CP_WAITALL();
    if (cur_rb >= 0) flush(cur_rb);
}

// ---------------------------------------------------------------------------
// loss
// ---------------------------------------------------------------------------
__global__ void loss_kernel(const float* __restrict__ Wo,
                            const float* __restrict__ bo,
                            const int* __restrict__ tags,
                            float* __restrict__ out) {
    const int warp = (blockIdx.x * blockDim.x + threadIdx.x) >> 5;
    const int lane = threadIdx.x & 31;
    const int nwarps = (gridDim.x * blockDim.x) >> 5;
    float local = 0.0f;
    for (int l = warp; l < L_; l += nwarps) {
        int tag = tags[l];
        float dot = 0.0f;
#pragma unroll
        for (int j = 0; j < 8; ++j) {
            int k = lane + j * 32;
            dot += g_feat[(size_t)l * 256 + k] * Wo[(size_t)k * V_ + tag];
        }
#pragma unroll
        for (int off = 16; off > 0; off >>= 1)
            dot += __shfl_down_sync(0xFFFFFFFFu, dot, off);
        if (lane == 0)
            local += logf(g_rowsum[l]) - (dot + bo[tag]);
    }
    if (lane == 0)
        atomicAdd(out, local * (1.0f / (4096.0f + 1e-5f)));
}

// ---------------------------------------------------------------------------
// Launch
// ---------------------------------------------------------------------------
extern "C" void kernel_launch(void* const* d_in, const int* in_sizes, int n_in,
                              void* d_out, int out_size) {
    const float* hidden = (const float*)d_in[0];
    const int*   begins = (const int*)d_in[1];
    const int*   ends   = (const int*)d_in[2];
    const int*   bids   = (const int*)d_in[3];
    const int*   tags   = (const int*)d_in[4];
    const float* W1     = (const float*)d_in[5];
    const float* b1     = (const float*)d_in[6];
    const float* W2     = (const float*)d_in[7];
    const float* b2     = (const float*)d_in[8];
    const float* Wo     = (const float*)d_in[9];
    const float* bo     = (const float*)d_in[10];
    float* out = (float*)d_out;

    __nv_bfloat16 *spanb, *h1b, *featb, *w1b, *w2b, *wob;
    float* feat;
    cudaGetSymbolAddress((void**)&spanb, g_spanb);
    cudaGetSymbolAddress((void**)&h1b, g_h1b);
    cudaGetSymbolAddress((void**)&feat, g_feat);
    cudaGetSymbolAddress((void**)&featb, g_featb);
    cudaGetSymbolAddress((void**)&w1b, g_w1b);
    cudaGetSymbolAddress((void**)&w2b, g_w2b);
    cudaGetSymbolAddress((void**)&wob, g_wob);

    cudaFuncSetAttribute(wgemm_kernel<3 * H_, 1>,
                         cudaFuncAttributeMaxDynamicSharedMemorySize,
                         WG_SMEM_BYTES);
    cudaFuncSetAttribute(wgemm_kernel<LAB_, 2>,
                         cudaFuncAttributeMaxDynamicSharedMemorySize,
                         WG_SMEM_BYTES);
    cudaFuncSetAttribute(cls_kernel,
                         cudaFuncAttributeMaxDynamicSharedMemorySize,
                         CLS_SMEM);

    prep_kernel<<<(N1_4 + N2_4 + 255) / 256, 256>>>(W1, W2, out);
    cvt_kernel<<<(LAB_ * V_ / 4 + 255) / 256, 256>>>(Wo, wob, LAB_ * V_ / 4);

    span_kernel<<<L_, 128>>>(hidden, begins, ends, bids);

    {
        dim3 grid(L_ / 64, LAB_ / 64);
        wgemm_kernel<3 * H_, 1><<<grid, 128, WG_SMEM_BYTES>>>(
            spanb, w1b, b1, nullptr, h1b, LAB_);
    }
    {
        dim3 grid(L_ / 64, LAB_ / 64);
        wgemm_kernel<LAB_, 2><<<grid, 128, WG_SMEM_BYTES>>>(
            h1b, w2b, b2, feat, featb, LAB_);
    }
    cls_kernel<<<CLS_GRID, 128, CLS_SMEM>>>(bo);

    loss_kernel<<<32, 256>>>(Wo, bo, tags, out);
}